// round 14
// baseline (speedup 1.0000x reference)
#include <cuda_runtime.h>
#include <cuda_fp16.h>
#include <math.h>

#define NU 60000
#define NI 120000
#define NT 180000   // NU + NI
#define NNZ_ADJ 3600000
#define NNZ_UG  960000
#define NNZ_IG  1920000

typedef unsigned long long ull;

// ---------------- device scratch ------------------------------------------------
__device__ float  g_spmm  [(size_t)NT * 64];
__device__ float  g_spmm_u[(size_t)NU * 64];
__device__ float  g_spmm_i[(size_t)NI * 64];
__device__ float  g_uh    [(size_t)NU * 64];
__device__ float  g_ih    [(size_t)NI * 64];
__device__ float  g_ego   [(size_t)NT * 64];   // fp32 ego (bi-term input)
__device__ float  g_all   [(size_t)NT * 256];
__device__ __half g_emb_h [(size_t)NT * 64];   // half embeddings [user ; item]
__device__ __half g_ego_h [(size_t)NT * 64];   // half ego (spmm input, layers 2-3)
__device__ __half g_hid_uh[(size_t)NU * 64];   // half user MLP hidden
__device__ __half g_hid_ih[(size_t)NI * 64];   // half item MLP hidden

// CSR storage: fused (col, val-bits) pairs
__device__ int2  g_adj_cv[NNZ_ADJ];
__device__ int   g_adj_rp[NT + 1];
__device__ int2  g_ug_cv [NNZ_UG];
__device__ int   g_ug_rp [NU + 1];
__device__ int2  g_ig_cv [NNZ_IG];
__device__ int   g_ig_rp [NI + 1];
// per-branch build scratch
__device__ int   g_counts_a[NT];
__device__ int   g_counts_u[NU];
__device__ int   g_counts_i[NI];
__device__ int   g_off_a   [NT];
__device__ int   g_off_u   [NU];
__device__ int   g_off_i   [NI];
__device__ ull   g_stat_a  [192];
__device__ ull   g_stat_u  [192];
__device__ ull   g_stat_i  [192];
__device__ int   g_tkt_a, g_tkt_u, g_tkt_i;

// ---------------- f32x2 helpers -------------------------------------------------
__device__ __forceinline__ ull pk2(float x, float y) {
    ull r; asm("mov.b64 %0, {%1, %2};" : "=l"(r) : "f"(x), "f"(y)); return r;
}
__device__ __forceinline__ void upk2(ull v, float& x, float& y) {
    asm("mov.b64 {%0, %1}, %2;" : "=f"(x), "=f"(y) : "l"(v));
}
__device__ __forceinline__ void fma2(ull& d, ull a, ull b) {
    asm("fma.rn.f32x2 %0, %1, %2, %0;" : "+l"(d) : "l"(a), "l"(b));
}
__device__ __forceinline__ unsigned h2u(float a, float b) {
    __half2 h = __floats2half2_rn(a, b);
    return *reinterpret_cast<unsigned*>(&h);
}

// ---------------- build reset: counts + lookback status + ticket ----------------
__global__ void reset_kernel(int4* __restrict__ counts, int n4,
                             ull* __restrict__ status, int* __restrict__ ticket) {
    int i = blockIdx.x * blockDim.x + threadIdx.x;
    int s = gridDim.x * blockDim.x;
    int4 z = make_int4(0, 0, 0, 0);
    for (int k = i; k < n4; k += s) counts[k] = z;
    if (i < 192) status[i] = 0ull;
    if (i == 0) *ticket = 0;
}

// ---------------- CSR build: histogram ------------------------------------------
__global__ void hist_kernel(const int* __restrict__ rows, int* __restrict__ counts, int nnz) {
    int i = blockIdx.x * blockDim.x + threadIdx.x;
    int s = gridDim.x * blockDim.x;
    for (; i < nnz; i += s) atomicAdd(counts + __ldg(rows + i), 1);
}

// ---------------- single-kernel decoupled-lookback exclusive scan ----------------
__global__ void __launch_bounds__(1024) scan_lookback_kernel(
    const int* __restrict__ counts, int* __restrict__ rowptr, int* __restrict__ off,
    ull* __restrict__ status, int* __restrict__ ticket, int n, int nnz) {
    __shared__ int ws[32];
    __shared__ int tile_s;
    __shared__ int exc_s;
    int tid = threadIdx.x, lane = tid & 31, w = tid >> 5;
    if (tid == 0) tile_s = atomicAdd(ticket, 1);
    __syncthreads();
    int tile = tile_s;

    int i = tile * 1024 + tid;
    int v = (i < n) ? counts[i] : 0;
    int x = v;
#pragma unroll
    for (int d = 1; d < 32; d <<= 1) {
        int y = __shfl_up_sync(0xffffffffu, x, d);
        if (lane >= d) x += y;
    }
    if (lane == 31) ws[w] = x;
    __syncthreads();
    if (w == 0) {
        int s = ws[lane];
#pragma unroll
        for (int d = 1; d < 32; d <<= 1) {
            int y = __shfl_up_sync(0xffffffffu, s, d);
            if (lane >= d) s += y;
        }
        ws[lane] = s;
    }
    __syncthreads();
    int T = ws[31];
    int local_excl = x - v + (w > 0 ? ws[w - 1] : 0);

    if (tid == 0) {
        if (tile == 0) {
            atomicExch(status + 0, ((ull)2 << 62) | (unsigned)T);
            exc_s = 0;
        } else {
            atomicExch(status + tile, ((ull)1 << 62) | (unsigned)T);
            int excl = 0;
            int p = tile - 1;
            while (true) {
                ull s;
                do { s = atomicAdd(status + p, 0ull); } while ((s >> 62) == 0);
                excl += (int)(s & 0xFFFFFFFFull);
                if ((s >> 62) == 2ull) break;
                p--;
            }
            exc_s = excl;
            atomicExch(status + tile, ((ull)2 << 62) | (unsigned)(excl + T));
        }
    }
    __syncthreads();
    int base = exc_s;
    if (i < n) {
        int e = base + local_excl;
        rowptr[i] = e;
        off[i]    = e;
    }
    if (tile == 0 && tid == 0) rowptr[n] = nnz;
}

// ---------------- CSR build: scatter (fused col+val) ----------------------------
__global__ void scatter_kernel(const int* __restrict__ rows, const int* __restrict__ cols,
                               const float* __restrict__ vals, int* __restrict__ off,
                               int2* __restrict__ cv, int nnz) {
    int i = blockIdx.x * blockDim.x + threadIdx.x;
    int s = gridDim.x * blockDim.x;
    for (; i < nnz; i += s) {
        int r = __ldg(rows + i);
        int p = atomicAdd(off + r, 1);
        cv[p] = make_int2(__ldg(cols + i), __float_as_int(__ldg(vals + i)));
    }
}

// ---------------- convert fp32 embeddings -> half -------------------------------
__global__ void to_half_kernel(const float4* __restrict__ ue, const float4* __restrict__ ie,
                               uint2* __restrict__ dst) {
    int i = blockIdx.x * blockDim.x + threadIdx.x;
    int s = gridDim.x * blockDim.x;
    const int tot = NT * 16;
    for (; i < tot; i += s) {
        int row = i >> 4;
        float4 v = (row < NU) ? ue[i] : ie[i - NU * 16];
        uint2 u;
        u.x = h2u(v.x, v.y);
        u.y = h2u(v.z, v.w);
        dst[i] = u;
    }
}

// ---------------- CSR SpMM: ONE WARP PER ROW, 2 cols/lane, no divergence --------
__global__ void __launch_bounds__(256) csr_spmmw_kernel(
    const int* __restrict__ rowptr, const int2* __restrict__ cv,
    const __half* __restrict__ x, float* __restrict__ out, int nrows) {
    int warp = (blockIdx.x * blockDim.x + threadIdx.x) >> 5;
    int lane = threadIdx.x & 31;
    if (warp >= nrows) return;
    int start = __ldg(rowptr + warp);
    int end   = __ldg(rowptr + warp + 1);

    float ax = 0.f, ay = 0.f;
    const unsigned* xb = reinterpret_cast<const unsigned*>(x);  // half2 words

    int j = start;
#define ACC(q, xw)                                                       \
    {                                                                    \
        float v = __int_as_float(q.y);                                   \
        float2 f = __half22float2(*reinterpret_cast<__half2*>(&xw));     \
        ax = fmaf(v, f.x, ax);                                           \
        ay = fmaf(v, f.y, ay);                                           \
    }
    for (; j + 4 <= end; j += 4) {
        int2 q0 = __ldg(cv + j);
        int2 q1 = __ldg(cv + j + 1);
        int2 q2 = __ldg(cv + j + 2);
        int2 q3 = __ldg(cv + j + 3);
        unsigned x0 = __ldg(xb + q0.x * 32 + lane);   // 4B/lane = 128B/warp = row
        unsigned x1 = __ldg(xb + q1.x * 32 + lane);
        unsigned x2 = __ldg(xb + q2.x * 32 + lane);
        unsigned x3 = __ldg(xb + q3.x * 32 + lane);
        ACC(q0, x0) ACC(q1, x1) ACC(q2, x2) ACC(q3, x3)
    }
    for (; j < end; j++) {
        int2 q = __ldg(cv + j);
        unsigned xw = __ldg(xb + q.x * 32 + lane);
        ACC(q, xw)
    }
#undef ACC
    *reinterpret_cast<float2*>(out + (size_t)warp * 64 + lane * 2) = make_float2(ax, ay);
}

// ---------------- GEMM: Y = act(X[R,64] @ W[64,64] + b), FFMA2 ------------------
template <int ACT, bool HOUT>
__global__ void __launch_bounds__(128) gemm64_kernel(
    const float* __restrict__ X, const float* __restrict__ W,
    const float* __restrict__ b, float* __restrict__ Y,
    __half* __restrict__ Yh, int R) {
    extern __shared__ float sm[];
    float* Ws = sm;           // 4096
    float* xs = sm + 4096;    // 8192 (transposed [k][tid])
    int tid = threadIdx.x;
    for (int i = tid; i < 4096; i += 128) Ws[i] = W[i];
    int row = blockIdx.x * 128 + tid;
    bool valid = row < R;
    if (valid) {
        const float4* xp = reinterpret_cast<const float4*>(X + (size_t)row * 64);
#pragma unroll
        for (int i = 0; i < 16; i++) {
            float4 t = xp[i];
            xs[(4 * i + 0) * 128 + tid] = t.x;
            xs[(4 * i + 1) * 128 + tid] = t.y;
            xs[(4 * i + 2) * 128 + tid] = t.z;
            xs[(4 * i + 3) * 128 + tid] = t.w;
        }
    }
    __syncthreads();
    if (!valid) return;

    ull acc2[32];
#pragma unroll
    for (int j = 0; j < 32; j++) acc2[j] = pk2(__ldg(b + 2 * j), __ldg(b + 2 * j + 1));

    for (int k = 0; k < 64; k++) {
        float xv = xs[k * 128 + tid];
        ull xv2 = pk2(xv, xv);
        const ulonglong2* wr = reinterpret_cast<const ulonglong2*>(Ws + k * 64);
#pragma unroll
        for (int j = 0; j < 16; j++) {
            ulonglong2 w = wr[j];
            fma2(acc2[2 * j + 0], xv2, w.x);
            fma2(acc2[2 * j + 1], xv2, w.y);
        }
    }

    float acc[64];
#pragma unroll
    for (int j = 0; j < 32; j++) upk2(acc2[j], acc[2 * j], acc[2 * j + 1]);
#pragma unroll
    for (int j = 0; j < 64; j++) {
        float a = acc[j];
        if (ACT == 1) a = a > 0.f ? a : expm1f(a);
        acc[j] = a;
    }

    if (HOUT) {
        uint4* yp = reinterpret_cast<uint4*>(Yh + (size_t)row * 64);
#pragma unroll
        for (int i = 0; i < 8; i++) {
            uint4 u;
            u.x = h2u(acc[8 * i + 0], acc[8 * i + 1]);
            u.y = h2u(acc[8 * i + 2], acc[8 * i + 3]);
            u.z = h2u(acc[8 * i + 4], acc[8 * i + 5]);
            u.w = h2u(acc[8 * i + 6], acc[8 * i + 7]);
            yp[i] = u;
        }
    } else {
        float4* yp = reinterpret_cast<float4*>(Y + (size_t)row * 64);
#pragma unroll
        for (int i = 0; i < 16; i++)
            yp[i] = make_float4(acc[4 * i + 0], acc[4 * i + 1], acc[4 * i + 2], acc[4 * i + 3]);
    }
}

// ---------------- Fused NGCF layer, FFMA2 ---------------------------------------
template <bool SPLIT>
__global__ void __launch_bounds__(128) layer_kernel(
    const float* __restrict__ Wg, const float* __restrict__ bg,
    const float* __restrict__ Wb, const float* __restrict__ bb,
    const float* __restrict__ eu, const float* __restrict__ ei, int kout) {
    extern __shared__ float sm[];
    float* Wgs = sm;            // 4096
    float* Wbs = sm + 4096;     // 4096
    float* ss  = sm + 8192;     // 8192 (transposed side [k][tid])
    int tid = threadIdx.x;
    for (int i = tid; i < 4096; i += 128) { Wgs[i] = Wg[i]; Wbs[i] = Wb[i]; }
    int row = blockIdx.x * 128 + tid;
    bool valid = row < NT;
    if (valid) {
        const float4* sp = reinterpret_cast<const float4*>(g_spmm + (size_t)row * 64);
#pragma unroll
        for (int i = 0; i < 16; i++) {
            float4 t = sp[i];
            ss[(4 * i + 0) * 128 + tid] = t.x;
            ss[(4 * i + 1) * 128 + tid] = t.y;
            ss[(4 * i + 2) * 128 + tid] = t.z;
            ss[(4 * i + 3) * 128 + tid] = t.w;
        }
    }
    __syncthreads();
    if (!valid) return;

    ull acc2[32];
#pragma unroll
    for (int j = 0; j < 32; j++)
        acc2[j] = pk2(__ldg(bg + 2 * j) + __ldg(bb + 2 * j),
                      __ldg(bg + 2 * j + 1) + __ldg(bb + 2 * j + 1));

    const float* erow;
    if (SPLIT) {
        erow = (row < NU) ? (eu + (size_t)row * 64) : (ei + (size_t)(row - NU) * 64);
    } else {
        erow = g_ego + (size_t)row * 64;
    }
    for (int k = 0; k < 64; k++) {
        float s = ss[k * 128 + tid];
        float p = s * __ldg(erow + k);
        ull s2 = pk2(s, s);
        ull p2 = pk2(p, p);
        const ulonglong2* wg = reinterpret_cast<const ulonglong2*>(Wgs + k * 64);
        const ulonglong2* wb = reinterpret_cast<const ulonglong2*>(Wbs + k * 64);
#pragma unroll
        for (int j = 0; j < 16; j++) {
            ulonglong2 a = wg[j];
            ulonglong2 c = wb[j];
            fma2(acc2[2 * j + 0], s2, a.x);
            fma2(acc2[2 * j + 1], s2, a.y);
            fma2(acc2[2 * j + 0], p2, c.x);
            fma2(acc2[2 * j + 1], p2, c.y);
        }
    }

    float acc[64];
#pragma unroll
    for (int j = 0; j < 32; j++) upk2(acc2[j], acc[2 * j], acc[2 * j + 1]);

    float ssum = 0.f;
#pragma unroll
    for (int j = 0; j < 64; j++) {
        float v = acc[j];
        v = v >= 0.f ? v : 0.2f * v;
        acc[j] = v;
        ssum += v * v;
    }
    float inv = 1.f / fmaxf(sqrtf(ssum), 1e-12f);

    float4* ep = reinterpret_cast<float4*>(g_ego + (size_t)row * 64);
    float4* ap = reinterpret_cast<float4*>(g_all + (size_t)row * 256 + (size_t)kout * 64);
#pragma unroll
    for (int i = 0; i < 16; i++) {
        float4 o = make_float4(acc[4 * i + 0], acc[4 * i + 1], acc[4 * i + 2], acc[4 * i + 3]);
        ep[i] = o;
        ap[i] = make_float4(o.x * inv, o.y * inv, o.z * inv, o.w * inv);
    }
    uint4* hp = reinterpret_cast<uint4*>(g_ego_h + (size_t)row * 64);
#pragma unroll
    for (int i = 0; i < 8; i++) {
        uint4 u;
        u.x = h2u(acc[8 * i + 0], acc[8 * i + 1]);
        u.y = h2u(acc[8 * i + 2], acc[8 * i + 3]);
        u.z = h2u(acc[8 * i + 4], acc[8 * i + 5]);
        u.w = h2u(acc[8 * i + 6], acc[8 * i + 7]);
        hp[i] = u;
    }
}

// ---------------- fill g_all block 0 (off critical path) ------------------------
__global__ void init_all0_kernel(const float4* __restrict__ ue, const float4* __restrict__ ie) {
    int i = blockIdx.x * blockDim.x + threadIdx.x;
    int s = gridDim.x * blockDim.x;
    const int tot = NT * 16;
    for (; i < tot; i += s) {
        int row = i >> 4;
        int c = i & 15;
        float4 v = (row < NU) ? ue[i] : ie[i - NU * 16];
        reinterpret_cast<float4*>(g_all)[(size_t)row * 64 + c] = v;
    }
}

// ---------------- final gather: out[12288, 320] ---------------------------------
__global__ void gather_kernel(const int* __restrict__ users, const int* __restrict__ pos,
                              const int* __restrict__ neg, float4* __restrict__ out) {
    int r = blockIdx.x;
    int tid = threadIdx.x;
    if (tid >= 80) return;
    const float4* allp;
    const float4* hp;
    if (r < 4096) {
        int u = __ldg(users + r);
        allp = reinterpret_cast<const float4*>(g_all + (size_t)u * 256);
        hp   = reinterpret_cast<const float4*>(g_uh + (size_t)u * 64);
    } else if (r < 8192) {
        int it = __ldg(pos + (r - 4096));
        allp = reinterpret_cast<const float4*>(g_all + ((size_t)NU + it) * 256);
        hp   = reinterpret_cast<const float4*>(g_ih + (size_t)it * 64);
    } else {
        int it = __ldg(neg + (r - 8192));
        allp = reinterpret_cast<const float4*>(g_all + ((size_t)NU + it) * 256);
        hp   = reinterpret_cast<const float4*>(g_ih + (size_t)it * 64);
    }
    float4 v;
    if (tid < 64) {
        v = allp[tid];
    } else {
        float4 h = hp[tid - 64];
        v = make_float4(fmaxf(h.x, 0.f), fmaxf(h.y, 0.f), fmaxf(h.z, 0.f), fmaxf(h.w, 0.f));
    }
    out[(size_t)r * 80 + tid] = v;
}

// ---------------- host ----------------------------------------------------------
static void build_csr(cudaStream_t st, const int* rows, const int* cols, const float* vals,
                      int nnz, int nrows, int* counts, int* off, int* rowptr,
                      ull* status, int* ticket, int2* cv) {
    int nb = (nrows + 1023) / 1024;
    reset_kernel<<<176, 256, 0, st>>>((int4*)counts, nrows / 4, status, ticket);
    hist_kernel<<<2048, 256, 0, st>>>(rows, counts, nnz);
    scan_lookback_kernel<<<nb, 1024, 0, st>>>(counts, rowptr, off, status, ticket, nrows, nnz);
    scatter_kernel<<<2048, 256, 0, st>>>(rows, cols, vals, off, cv, nnz);
}

#define GEMM_SMEM  (12288 * 4)   // 48 KB
#define LAYER_SMEM (16384 * 4)   // 64 KB

extern "C" void kernel_launch(void* const* d_in, const int* in_sizes, int n_in,
                              void* d_out, int out_size) {
    const int*   users    = (const int*)d_in[0];
    const int*   pos      = (const int*)d_in[1];
    const int*   neg      = (const int*)d_in[2];
    const int*   adj_r    = (const int*)d_in[3];
    const int*   adj_c    = (const int*)d_in[4];
    const float* adj_v    = (const float*)d_in[5];
    const int*   ug_r     = (const int*)d_in[6];
    const int*   ug_c     = (const int*)d_in[7];
    const float* ug_v     = (const float*)d_in[8];
    const int*   ig_r     = (const int*)d_in[9];
    const int*   ig_c     = (const int*)d_in[10];
    const float* ig_v     = (const float*)d_in[11];
    const float* user_emb = (const float*)d_in[12];
    const float* item_emb = (const float*)d_in[13];
    const float* W_gc     = (const float*)d_in[14];
    const float* b_gc     = (const float*)d_in[15];
    const float* W_bi     = (const float*)d_in[16];
    const float* b_bi     = (const float*)d_in[17];
    const float* Wu0      = (const float*)d_in[18];
    const float* bu0      = (const float*)d_in[19];
    const float* Wu1      = (const float*)d_in[20];
    const float* bu1      = (const float*)d_in[21];
    const float* Wi0      = (const float*)d_in[22];
    const float* bi0      = (const float*)d_in[23];
    const float* Wi1      = (const float*)d_in[24];
    const float* bi1      = (const float*)d_in[25];

    const int nnz_adj = in_sizes[3];
    const int nnz_ug  = in_sizes[6];
    const int nnz_ig  = in_sizes[9];

    static cudaStream_t s1 = nullptr, s2 = nullptr, s3 = nullptr;
    static cudaEvent_t evR = nullptr, ev1 = nullptr, ev2 = nullptr, ev3 = nullptr;
    if (s1 == nullptr) {
        cudaStreamCreateWithFlags(&s1, cudaStreamNonBlocking);
        cudaStreamCreateWithFlags(&s2, cudaStreamNonBlocking);
        cudaStreamCreateWithFlags(&s3, cudaStreamNonBlocking);
        cudaEventCreateWithFlags(&evR, cudaEventDisableTiming);
        cudaEventCreateWithFlags(&ev1, cudaEventDisableTiming);
        cudaEventCreateWithFlags(&ev2, cudaEventDisableTiming);
        cudaEventCreateWithFlags(&ev3, cudaEventDisableTiming);
        cudaFuncSetAttribute(gemm64_kernel<0, false>, cudaFuncAttributeMaxDynamicSharedMemorySize, GEMM_SMEM);
        cudaFuncSetAttribute(gemm64_kernel<1, true>,  cudaFuncAttributeMaxDynamicSharedMemorySize, GEMM_SMEM);
        cudaFuncSetAttribute(layer_kernel<true>,  cudaFuncAttributeMaxDynamicSharedMemorySize, LAYER_SMEM);
        cudaFuncSetAttribute(layer_kernel<false>, cudaFuncAttributeMaxDynamicSharedMemorySize, LAYER_SMEM);
    }

    float *spmm_p, *spmm_u, *spmm_i, *uh_p, *ih_p;
    __half *emb_h, *ego_h, *hid_uh, *hid_ih;
    cudaGetSymbolAddress((void**)&spmm_p, g_spmm);
    cudaGetSymbolAddress((void**)&spmm_u, g_spmm_u);
    cudaGetSymbolAddress((void**)&spmm_i, g_spmm_i);
    cudaGetSymbolAddress((void**)&uh_p,   g_uh);
    cudaGetSymbolAddress((void**)&ih_p,   g_ih);
    cudaGetSymbolAddress((void**)&emb_h,  g_emb_h);
    cudaGetSymbolAddress((void**)&ego_h,  g_ego_h);
    cudaGetSymbolAddress((void**)&hid_uh, g_hid_uh);
    cudaGetSymbolAddress((void**)&hid_ih, g_hid_ih);

    int *cnt_a, *cnt_u, *cnt_i, *off_a, *off_u, *off_i;
    int *adj_rp, *ug_rp, *ig_rp;
    int2 *adj_cv, *ug_cv, *ig_cv;
    ull *st_a, *st_u, *st_i;
    int *tk_a, *tk_u, *tk_i;
    cudaGetSymbolAddress((void**)&cnt_a, g_counts_a);
    cudaGetSymbolAddress((void**)&cnt_u, g_counts_u);
    cudaGetSymbolAddress((void**)&cnt_i, g_counts_i);
    cudaGetSymbolAddress((void**)&off_a, g_off_a);
    cudaGetSymbolAddress((void**)&off_u, g_off_u);
    cudaGetSymbolAddress((void**)&off_i, g_off_i);
    cudaGetSymbolAddress((void**)&adj_rp, g_adj_rp);
    cudaGetSymbolAddress((void**)&ug_rp,  g_ug_rp);
    cudaGetSymbolAddress((void**)&ig_rp,  g_ig_rp);
    cudaGetSymbolAddress((void**)&adj_cv, g_adj_cv);
    cudaGetSymbolAddress((void**)&ug_cv,  g_ug_cv);
    cudaGetSymbolAddress((void**)&ig_cv,  g_ig_cv);
    cudaGetSymbolAddress((void**)&st_a,   g_stat_a);
    cudaGetSymbolAddress((void**)&st_u,   g_stat_u);
    cudaGetSymbolAddress((void**)&st_i,   g_stat_i);
    cudaGetSymbolAddress((void**)&tk_a,   g_tkt_a);
    cudaGetSymbolAddress((void**)&tk_u,   g_tkt_u);
    cudaGetSymbolAddress((void**)&tk_i,   g_tkt_i);

    // ---- fork events first ----
    cudaEventRecord(evR, 0);
    cudaStreamWaitEvent(s1, evR, 0);
    cudaStreamWaitEvent(s2, evR, 0);
    cudaStreamWaitEvent(s3, evR, 0);

    // ---- s3: fp32 -> half embedding conversion ----
    to_half_kernel<<<1024, 256, 0, s3>>>((const float4*)user_emb, (const float4*)item_emb,
                                         (uint2*)emb_h);
    cudaEventRecord(ev3, s3);

    // ---- main stream: critical path FIRST ----
    build_csr(0, adj_r, adj_c, adj_v, nnz_adj, NT, cnt_a, off_a, adj_rp, st_a, tk_a, adj_cv);
    cudaStreamWaitEvent(0, ev3, 0);
    csr_spmmw_kernel<<<(NT * 32 + 255) / 256, 256>>>(adj_rp, adj_cv, emb_h, spmm_p, NT);
    layer_kernel<true><<<(NT + 127) / 128, 128, LAYER_SMEM>>>(
        W_gc, b_gc, W_bi, b_bi, user_emb, item_emb, 1);
    for (int k = 1; k < 3; k++) {
        csr_spmmw_kernel<<<(NT * 32 + 255) / 256, 256>>>(adj_rp, adj_cv, ego_h, spmm_p, NT);
        layer_kernel<false><<<(NT + 127) / 128, 128, LAYER_SMEM>>>(
            W_gc + (size_t)k * 4096, b_gc + (size_t)k * 64,
            W_bi + (size_t)k * 4096, b_bi + (size_t)k * 64, nullptr, nullptr, k + 1);
    }

    // ---- branch 1 (s1): g_all block0 + user MLP path ----
    init_all0_kernel<<<1024, 256, 0, s1>>>((const float4*)user_emb, (const float4*)item_emb);
    build_csr(s1, ug_r, ug_c, ug_v, nnz_ug, NU, cnt_u, off_u, ug_rp, st_u, tk_u, ug_cv);
    cudaStreamWaitEvent(s1, ev3, 0);
    csr_spmmw_kernel<<<(NU * 32 + 255) / 256, 256, 0, s1>>>(ug_rp, ug_cv, emb_h, spmm_u, NU);
    gemm64_kernel<1, true><<<(NU + 127) / 128, 128, GEMM_SMEM, s1>>>(spmm_u, Wu0, bu0, nullptr, hid_uh, NU);
    csr_spmmw_kernel<<<(NU * 32 + 255) / 256, 256, 0, s1>>>(ug_rp, ug_cv, hid_uh, spmm_u, NU);
    gemm64_kernel<0, false><<<(NU + 127) / 128, 128, GEMM_SMEM, s1>>>(spmm_u, Wu1, bu1, uh_p, nullptr, NU);
    cudaEventRecord(ev1, s1);

    // ---- branch 2 (s2): item MLP path ----
    build_csr(s2, ig_r, ig_c, ig_v, nnz_ig, NI, cnt_i, off_i, ig_rp, st_i, tk_i, ig_cv);
    cudaStreamWaitEvent(s2, ev3, 0);
    csr_spmmw_kernel<<<(NI * 32 + 255) / 256, 256, 0, s2>>>(ig_rp, ig_cv, emb_h + (size_t)NU * 64, spmm_i, NI);
    gemm64_kernel<1, true><<<(NI + 127) / 128, 128, GEMM_SMEM, s2>>>(spmm_i, Wi0, bi0, nullptr, hid_ih, NI);
    csr_spmmw_kernel<<<(NI * 32 + 255) / 256, 256, 0, s2>>>(ig_rp, ig_cv, hid_ih, spmm_i, NI);
    gemm64_kernel<0, false><<<(NI + 127) / 128, 128, GEMM_SMEM, s2>>>(spmm_i, Wi1, bi1, ih_p, nullptr, NI);
    cudaEventRecord(ev2, s2);

    // ---- join + final gather ----
    cudaStreamWaitEvent(0, ev1, 0);
    cudaStreamWaitEvent(0, ev2, 0);
    gather_kernel<<<12288, 96>>>(users, pos, neg, (float4*)d_out);
}